// round 17
// baseline (speedup 1.0000x reference)
#include <cuda_runtime.h>

// y[b,c] = b_fc[c] + dot(h[b,0,:], V[c,:]),  V = W_fc @ W_emb  ([2,768])
// (TreeLSTM scan in the reference is dead code; adj and recurrent weights unused.)
// B=32, N=128, FI=768, FO=128.
//
// Two nodes with Programmatic Dependent Launch. R16 showed B's CTA count is
// the live gradient (32->8 CTAs: 6.66->6.27). R17: B at 4 CTAs x 768 threads
// (8 batches/CTA, 96 threads/batch, 2 quads/thread). A unchanged (R7 body).

#define B_  32
#define N_  128
#define FI_ 768
#define FO_ 128

__device__ float g_V[2][FI_];   // scratch: V = W_fc @ W_emb

// ---- Kernel A (exactly R7): V[c,f] = sum_o W_fc[c,o] * W_emb[o,f] ----
__global__ __launch_bounds__(256, 1)
void rvnn_precompute_V(const float* __restrict__ W_emb,  // [FO,FI]
                       const float* __restrict__ W_fc)   // [2,FO]
{
    cudaTriggerProgrammaticLaunchCompletion();

    const int t  = threadIdx.x;
    const int fl = t & 31;        // f within block
    const int g  = t >> 5;        // o-chunk 0..7
    const int f  = blockIdx.x * 32 + fl;

    float a0 = 0.0f, a1 = 0.0f;
    #pragma unroll
    for (int j = 0; j < 16; ++j) {
        const int o = g * 16 + j;
        float w = __ldg(&W_emb[(size_t)o * FI_ + f]);   // coalesced across lanes
        a0 = fmaf(__ldg(&W_fc[o]),       w, a0);
        a1 = fmaf(__ldg(&W_fc[FO_ + o]), w, a1);
    }

    __shared__ float sp0[8][32], sp1[8][32];
    sp0[g][fl] = a0;
    sp1[g][fl] = a1;
    __syncthreads();

    if (t < 32) {
        float s = 0.0f;
        #pragma unroll
        for (int k = 0; k < 8; ++k) s += sp0[k][t];
        g_V[0][blockIdx.x * 32 + t] = s;
    } else if (t < 64) {
        const int l = t - 32;
        float s = 0.0f;
        #pragma unroll
        for (int k = 0; k < 8; ++k) s += sp1[k][l];
        g_V[1][blockIdx.x * 32 + l] = s;
    }
}

// ---- Kernel B: 4 CTAs x 768 threads, 8 batches per CTA ----
// Batch slot = 96 threads = 3 warps (aligned). Each thread: quads tt, tt+96.
__global__ __launch_bounds__(768, 1)
void rvnn_head_kernel(const float* __restrict__ h,    // [B,N,FI]
                      const float* __restrict__ b_fc, // [2]
                      float* __restrict__ y)          // [B,2]
{
    const int t    = threadIdx.x;            // 0..767
    const int sub  = t / 96;                 // 0..7 (batch slot)
    const int tt   = t - sub * 96;           // 0..95
    const int b    = blockIdx.x * 8 + sub;   // batch
    const int wib  = tt >> 5;                // warp in batch 0..2
    const int lane = t & 31;

    // h + bias loads issue while kernel A is still running (PDL overlap).
    const float4* hrow = reinterpret_cast<const float4*>(h + (size_t)b * N_ * FI_);
    float4 ha = __ldg(&hrow[tt]);
    float4 hb = __ldg(&hrow[tt + 96]);
    const float bf0 = __ldg(&b_fc[0]);
    const float bf1 = __ldg(&b_fc[1]);

    cudaGridDependencySynchronize();         // wait for A's g_V writes

    float4 v0a = *reinterpret_cast<const float4*>(&g_V[0][tt * 4]);
    float4 v1a = *reinterpret_cast<const float4*>(&g_V[1][tt * 4]);
    float4 v0b = *reinterpret_cast<const float4*>(&g_V[0][(tt + 96) * 4]);
    float4 v1b = *reinterpret_cast<const float4*>(&g_V[1][(tt + 96) * 4]);

    float a0 = fmaf(ha.x, v0a.x, fmaf(ha.y, v0a.y, fmaf(ha.z, v0a.z, ha.w * v0a.w)));
    a0 = fmaf(hb.x, v0b.x, fmaf(hb.y, v0b.y, fmaf(hb.z, v0b.z, fmaf(hb.w, v0b.w, a0))));
    float a1 = fmaf(ha.x, v1a.x, fmaf(ha.y, v1a.y, fmaf(ha.z, v1a.z, ha.w * v1a.w)));
    a1 = fmaf(hb.x, v1b.x, fmaf(hb.y, v1b.y, fmaf(hb.z, v1b.z, fmaf(hb.w, v1b.w, a1))));

    #pragma unroll
    for (int off = 16; off > 0; off >>= 1) {
        a0 += __shfl_down_sync(0xffffffffu, a0, off);
        a1 += __shfl_down_sync(0xffffffffu, a1, off);
    }

    __shared__ float w0[8][3], w1[8][3];
    if (lane == 0) { w0[sub][wib] = a0; w1[sub][wib] = a1; }
    __syncthreads();

    if (tt == 0) {
        float s0 = w0[sub][0] + w0[sub][1] + w0[sub][2];
        float s1 = w1[sub][0] + w1[sub][1] + w1[sub][2];
        y[b * 2 + 0] = s0 + bf0;
        y[b * 2 + 1] = s1 + bf1;
    }
}

extern "C" void kernel_launch(void* const* d_in, const int* in_sizes, int n_in,
                              void* d_out, int out_size)
{
    // metadata order: h, adj, W_emb, W_ioux, b_ioux, W_iouh, b_iouh,
    //                 W_coux, b_coux, W_couh, b_couh, W_fc, b_fc
    const float* h     = (const float*)d_in[0];
    const float* W_emb = (const float*)d_in[2];
    const float* W_fc  = (const float*)d_in[11];
    const float* b_fc  = (const float*)d_in[12];
    float* y = (float*)d_out;

    rvnn_precompute_V<<<FI_ / 32, 256>>>(W_emb, W_fc);   // 24 blocks (R7)

    cudaLaunchConfig_t cfg = {};
    cfg.gridDim  = dim3(B_ / 8, 1, 1);    // 4 CTAs
    cfg.blockDim = dim3(768, 1, 1);
    cfg.dynamicSmemBytes = 0;
    cfg.stream = 0;
    cudaLaunchAttribute attrs[1];
    attrs[0].id = cudaLaunchAttributeProgrammaticStreamSerialization;
    attrs[0].val.programmaticStreamSerializationAllowed = 1;
    cfg.attrs = attrs;
    cfg.numAttrs = 1;
    cudaLaunchKernelEx(&cfg, rvnn_head_kernel, h, b_fc, y);
}